// round 15
// baseline (speedup 1.0000x reference)
#include <cuda_runtime.h>
#include <cstdint>

#define N_NODES   50000
#define IN_FEAT   128
#define OUT_FEAT  128
#define NB        16
#define SI        8
#define SO        8
#define W_PER_REL (NB * SI * SO)   // 1024
#define E_MAX     500000
#define MAXR      200
#define NBLK2     232               // one wave of fat sort blocks
#define SORT_TPB  256
#define EPW       8                 // edges per warp in edge kernel
#define GM_ROWS   64

// Scratch (static device globals — allocation-free per harness rules)
__device__ int4 g_edges[E_MAX];            // (src, dst, etype, norm_bits), etype-sorted
__device__ int  g_bh[MAXR * NBLK2];        // per-(rel, block) counts
__device__ int  g_off[MAXR * NBLK2];       // per-(rel, block) exclusive base offsets

// ---------------------------------------------------------------------------
__device__ __forceinline__ void red_add_v4(float* addr, float4 v) {
    asm volatile("red.global.add.v4.f32 [%0], {%1, %2, %3, %4};"
                 :: "l"(addr), "f"(v.x), "f"(v.y), "f"(v.z), "f"(v.w)
                 : "memory");
}

// Packed 2xfp32 FMA (sm_100a)
__device__ __forceinline__ uint64_t pack2(float lo, float hi) {
    uint64_t r;
    asm("mov.b64 %0, {%1, %2};" : "=l"(r) : "f"(lo), "f"(hi));
    return r;
}
__device__ __forceinline__ void unpack2(uint64_t v, float& lo, float& hi) {
    asm("mov.b64 {%0, %1}, %2;" : "=f"(lo), "=f"(hi) : "l"(v));
}
__device__ __forceinline__ void ffma2(uint64_t& d, uint64_t a, uint64_t b) {
    asm("fma.rn.f32x2 %0, %1, %2, %0;" : "+l"(d) : "l"(a), "l"(b));
}

// ---------------------------------------------------------------------------
// Pass 1: per-block histogram over contiguous edge chunk (grid = NBLK2)
// Also zeroes d_out so the edge kernel can RED directly into it.
// ---------------------------------------------------------------------------
__global__ __launch_bounds__(SORT_TPB) void k_hist(const int* __restrict__ et,
                                                   float* __restrict__ out,
                                                   int n, int chunk) {
    __shared__ int sh[MAXR];
    int tid = threadIdx.x, bid = blockIdx.x;
    if (tid < MAXR) sh[tid] = 0;
    __syncthreads();

    // zero d_out (grid-stride float4)
    {
        float4* out4 = reinterpret_cast<float4*>(out);
        int total4 = N_NODES * OUT_FEAT / 4;
        for (int i = bid * SORT_TPB + tid; i < total4; i += NBLK2 * SORT_TPB)
            out4[i] = make_float4(0.f, 0.f, 0.f, 0.f);
    }

    int lo = bid * chunk;
    int hi = lo + chunk; if (hi > n) hi = n;
    for (int e = lo + tid; e < hi; e += SORT_TPB)
        atomicAdd(&sh[et[e]], 1);
    __syncthreads();
    if (tid < MAXR) g_bh[tid * NBLK2 + bid] = sh[tid];
}

// ---------------------------------------------------------------------------
// Pass 2 (merged): grid = MAXR blocks. Block r:
//   base  = sum of g_bh rows q < r (redundant, L2-resident)
//   off[r][b] = base + exclusive prefix of own row
// Writes g_off (separate array -> no read/write race across blocks).
// ---------------------------------------------------------------------------
__global__ __launch_bounds__(256) void k_scanall() {
    __shared__ int sh[256];
    int r = blockIdx.x, tid = threadIdx.x;

    // partial sums over all preceding rows
    long long part = 0;
    if (tid < NBLK2) {
        for (int q = 0; q < r; q++)
            part += g_bh[q * NBLK2 + tid];
    }
    sh[tid] = (int)part;
    __syncthreads();
    for (int off = 128; off > 0; off >>= 1) {
        if (tid < off) sh[tid] += sh[tid + off];
        __syncthreads();
    }
    int base = sh[0];
    __syncthreads();

    // exclusive scan of own row (Hillis-Steele over 256; NBLK2 entries)
    int v = (tid < NBLK2) ? g_bh[r * NBLK2 + tid] : 0;
    sh[tid] = v;
    __syncthreads();
    for (int off = 1; off < 256; off <<= 1) {
        int x = (tid >= off) ? sh[tid - off] : 0;
        __syncthreads();
        sh[tid] += x;
        __syncthreads();
    }
    if (tid < NBLK2) g_off[r * NBLK2 + tid] = base + sh[tid] - v;
}

// ---------------------------------------------------------------------------
// Pass 3: scatter with shared cursors (no global atomics)
// ---------------------------------------------------------------------------
__global__ __launch_bounds__(SORT_TPB) void k_scatter(const int* __restrict__ src,
                                                      const int* __restrict__ dst,
                                                      const int* __restrict__ et,
                                                      const float* __restrict__ norm,
                                                      int n, int chunk) {
    __shared__ int cur[MAXR];
    int tid = threadIdx.x, bid = blockIdx.x;
    if (tid < MAXR) cur[tid] = g_off[tid * NBLK2 + bid];
    __syncthreads();
    int lo = bid * chunk;
    int hi = lo + chunk; if (hi > n) hi = n;
    for (int e = lo + tid; e < hi; e += SORT_TPB) {
        int t = et[e];
        int d = dst[e];
        int s = src[e];
        float nv = __ldg(norm + d);
        int pos = atomicAdd(&cur[t], 1);
        int4 ed;
        ed.x = s;
        ed.y = d;
        ed.z = t;
        ed.w = __float_as_int(nv);
        g_edges[pos] = ed;
    }
}

// ---------------------------------------------------------------------------
// Edge kernel (R3 champion form, EPW=8): warp processes EPW consecutive
// etype-sorted edges; W cached in registers; RED.v4 into d_out (zeroed).
//   lane l: basis block b = l>>1, output offset o0 = (l&1)*4
// ---------------------------------------------------------------------------
__global__ __launch_bounds__(256) void edge_kernel(
        const float* __restrict__ h,
        const float* __restrict__ weight,
        float* __restrict__ out,
        int nedges) {
    int gw   = (blockIdx.x * blockDim.x + threadIdx.x) >> 5;
    int lane = threadIdx.x & 31;
    int e0 = gw * EPW;
    if (e0 >= nedges) return;            // warp-uniform

    int b  = lane >> 1;
    int o0 = (lane & 1) * 4;

    int t_cur = -1;
    float4 w[SI];

    int e_end = e0 + EPW;
    if (e_end > nedges) e_end = nedges;

    for (int e = e0; e < e_end; e++) {
        int4 ed = g_edges[e];                 // warp-uniform broadcast load
        int s = ed.x, d = ed.y, t = ed.z;
        float nrm = __int_as_float(ed.w);

        if (t != t_cur) {                     // warp-uniform branch (rare)
            t_cur = t;
            const float* wb = weight + (size_t)t * W_PER_REL + b * (SI * SO) + o0;
#pragma unroll
            for (int i = 0; i < SI; i++)
                w[i] = __ldg(reinterpret_cast<const float4*>(wb + i * SO));
        }

        const float4* xp = reinterpret_cast<const float4*>(h + (size_t)s * IN_FEAT + b * SI);
        float4 xa = __ldg(xp);
        float4 xb = __ldg(xp + 1);
        float x[8] = {xa.x, xa.y, xa.z, xa.w, xb.x, xb.y, xb.z, xb.w};

        float4 acc = make_float4(0.f, 0.f, 0.f, 0.f);
#pragma unroll
        for (int i = 0; i < SI; i++) {
            acc.x = fmaf(x[i], w[i].x, acc.x);
            acc.y = fmaf(x[i], w[i].y, acc.y);
            acc.z = fmaf(x[i], w[i].z, acc.z);
            acc.w = fmaf(x[i], w[i].w, acc.w);
        }

        acc.x *= nrm; acc.y *= nrm; acc.z *= nrm; acc.w *= nrm;
        red_add_v4(out + (size_t)d * OUT_FEAT + lane * 4, acc);
    }
}

// ---------------------------------------------------------------------------
// GEMM + add + ReLU (runs LAST): out = relu(h @ lw + out)  — f32x2 FMA.
// 64 rows x 128 cols per block, 256 threads -> thread = 8 rows x 4 cols.
// ---------------------------------------------------------------------------
__global__ __launch_bounds__(256) void gemm_add_relu_kernel(
        const float* __restrict__ h,
        const float* __restrict__ lw,
        float* __restrict__ out) {
    __shared__ float4 xs[GM_ROWS][32];   // 32KB tile of h
    int r0 = blockIdx.x * GM_ROWS;
    int tid = threadIdx.x;

    const float4* h4 = reinterpret_cast<const float4*>(h);
    for (int idx = tid; idx < GM_ROWS * 32; idx += 256) {
        int r = idx >> 5, c = idx & 31;
        int gr = r0 + r;
        xs[r][c] = (gr < N_NODES) ? __ldg(&h4[(size_t)gr * 32 + c])
                                  : make_float4(0.f, 0.f, 0.f, 0.f);
    }
    __syncthreads();

    int cx = tid & 31;          // float4 col index (cols 4cx..4cx+3)
    int rg = (tid >> 5) * 8;    // row base within tile

    uint64_t accA[8], accB[8];
#pragma unroll
    for (int r = 0; r < 8; r++) { accA[r] = 0ull; accB[r] = 0ull; }

    const float4* lw4 = reinterpret_cast<const float4*>(lw);

    for (int k4 = 0; k4 < 32; k4++) {        // 4 k-values per iteration
        float4 w0 = __ldg(&lw4[(size_t)(k4 * 4 + 0) * 32 + cx]);
        float4 w1 = __ldg(&lw4[(size_t)(k4 * 4 + 1) * 32 + cx]);
        float4 w2 = __ldg(&lw4[(size_t)(k4 * 4 + 2) * 32 + cx]);
        float4 w3 = __ldg(&lw4[(size_t)(k4 * 4 + 3) * 32 + cx]);
        uint64_t wA0 = pack2(w0.x, w0.y), wB0 = pack2(w0.z, w0.w);
        uint64_t wA1 = pack2(w1.x, w1.y), wB1 = pack2(w1.z, w1.w);
        uint64_t wA2 = pack2(w2.x, w2.y), wB2 = pack2(w2.z, w2.w);
        uint64_t wA3 = pack2(w3.x, w3.y), wB3 = pack2(w3.z, w3.w);
#pragma unroll
        for (int r = 0; r < 8; r++) {
            float4 xv = xs[rg + r][k4];      // warp-broadcast LDS.128
            uint64_t xx;
            xx = pack2(xv.x, xv.x); ffma2(accA[r], xx, wA0); ffma2(accB[r], xx, wB0);
            xx = pack2(xv.y, xv.y); ffma2(accA[r], xx, wA1); ffma2(accB[r], xx, wB1);
            xx = pack2(xv.z, xv.z); ffma2(accA[r], xx, wA2); ffma2(accB[r], xx, wB2);
            xx = pack2(xv.w, xv.w); ffma2(accA[r], xx, wA3); ffma2(accB[r], xx, wB3);
        }
    }

    float4* out4 = reinterpret_cast<float4*>(out);
#pragma unroll
    for (int r = 0; r < 8; r++) {
        int gr = r0 + rg + r;
        if (gr < N_NODES) {
            size_t idx = (size_t)gr * 32 + cx;
            float4 agg = out4[idx];           // edge aggregation (norm-scaled)
            float4 v;
            float a0, a1, b0, b1;
            unpack2(accA[r], a0, a1);
            unpack2(accB[r], b0, b1);
            v.x = fmaxf(a0 + agg.x, 0.f);
            v.y = fmaxf(a1 + agg.y, 0.f);
            v.z = fmaxf(b0 + agg.z, 0.f);
            v.w = fmaxf(b1 + agg.w, 0.f);
            out4[idx] = v;
        }
    }
}

// ---------------------------------------------------------------------------
// Launch (5 kernels): hist(+zero out) -> scanall -> scatter
//                     -> edge(RED into out) -> gemm+add+relu
// Inputs (metadata order): h, norm, weight, loop_weight, src, dst, etype
// ---------------------------------------------------------------------------
extern "C" void kernel_launch(void* const* d_in, const int* in_sizes, int n_in,
                              void* d_out, int out_size) {
    const float* h      = (const float*)d_in[0];
    const float* norm   = (const float*)d_in[1];
    const float* weight = (const float*)d_in[2];
    const float* lw     = (const float*)d_in[3];
    const int*   src    = (const int*)d_in[4];
    const int*   dst    = (const int*)d_in[5];
    const int*   etype  = (const int*)d_in[6];
    float* out = (float*)d_out;

    int nedges = in_sizes[4];
    if (nedges > E_MAX) nedges = E_MAX;
    int chunk = (nedges + NBLK2 - 1) / NBLK2;

    // ---- counting sort by etype (hist also zeroes d_out) ----
    k_hist<<<NBLK2, SORT_TPB>>>(etype, out, nedges, chunk);
    k_scanall<<<MAXR, 256>>>();
    k_scatter<<<NBLK2, SORT_TPB>>>(src, dst, etype, norm, nedges, chunk);

    // ---- per-edge messages, RED directly into d_out ----
    {
        int nwarps = (nedges + EPW - 1) / EPW;
        int blocks = (nwarps + 7) / 8;       // 8 warps / block
        edge_kernel<<<blocks, 256>>>(h, weight, out, nedges);
    }

    // ---- self-loop GEMM + add + ReLU (final pass) ----
    gemm_add_relu_kernel<<<(N_NODES + GM_ROWS - 1) / GM_ROWS, 256>>>(h, lw, out);
}

// round 16
// speedup vs baseline: 1.0965x; 1.0965x over previous
#include <cuda_runtime.h>
#include <cstdint>

#define N_NODES   50000
#define IN_FEAT   128
#define OUT_FEAT  128
#define NB        16
#define SI        8
#define SO        8
#define W_PER_REL (NB * SI * SO)   // 1024
#define E_MAX     500000
#define MAXR      200
#define NBLK2     232               // one wave of fat sort blocks
#define SORT_TPB  256
#define EPW       16                // edges per warp (measured: 16 beats 8)
#define GM_ROWS   64

// Scratch (static device globals — allocation-free per harness rules)
__device__ int4 g_edges[E_MAX];            // (src, dst, etype, norm_bits), etype-sorted
__device__ int  g_bh[MAXR * NBLK2];        // per-(rel, block) counts
__device__ int  g_off[MAXR * NBLK2];       // per-(rel, block) exclusive base offsets

// ---------------------------------------------------------------------------
__device__ __forceinline__ void red_add_v4(float* addr, float4 v) {
    asm volatile("red.global.add.v4.f32 [%0], {%1, %2, %3, %4};"
                 :: "l"(addr), "f"(v.x), "f"(v.y), "f"(v.z), "f"(v.w)
                 : "memory");
}

// Packed 2xfp32 FMA (sm_100a)
__device__ __forceinline__ uint64_t pack2(float lo, float hi) {
    uint64_t r;
    asm("mov.b64 %0, {%1, %2};" : "=l"(r) : "f"(lo), "f"(hi));
    return r;
}
__device__ __forceinline__ void unpack2(uint64_t v, float& lo, float& hi) {
    asm("mov.b64 {%0, %1}, %2;" : "=f"(lo), "=f"(hi) : "l"(v));
}
__device__ __forceinline__ void ffma2(uint64_t& d, uint64_t a, uint64_t b) {
    asm("fma.rn.f32x2 %0, %1, %2, %0;" : "+l"(d) : "l"(a), "l"(b));
}

// ---------------------------------------------------------------------------
// Pass 1: per-block histogram over contiguous edge chunk (grid = NBLK2)
// Also zeroes d_out so the edge kernel can RED directly into it.
// ---------------------------------------------------------------------------
__global__ __launch_bounds__(SORT_TPB) void k_hist(const int* __restrict__ et,
                                                   float* __restrict__ out,
                                                   int n, int chunk) {
    __shared__ int sh[MAXR];
    int tid = threadIdx.x, bid = blockIdx.x;
    if (tid < MAXR) sh[tid] = 0;
    __syncthreads();

    // zero d_out (grid-stride float4)
    {
        float4* out4 = reinterpret_cast<float4*>(out);
        int total4 = N_NODES * OUT_FEAT / 4;
        for (int i = bid * SORT_TPB + tid; i < total4; i += NBLK2 * SORT_TPB)
            out4[i] = make_float4(0.f, 0.f, 0.f, 0.f);
    }

    int lo = bid * chunk;
    int hi = lo + chunk; if (hi > n) hi = n;
    for (int e = lo + tid; e < hi; e += SORT_TPB)
        atomicAdd(&sh[et[e]], 1);
    __syncthreads();
    if (tid < MAXR) g_bh[tid * NBLK2 + bid] = sh[tid];
}

// ---------------------------------------------------------------------------
// Pass 2 (merged): grid = MAXR blocks. Block r:
//   base  = sum of g_bh rows q < r (redundant, L2-resident)
//   off[r][b] = base + exclusive prefix of own row
// Writes g_off (separate array -> no read/write race across blocks).
// ---------------------------------------------------------------------------
__global__ __launch_bounds__(256) void k_scanall() {
    __shared__ int sh[256];
    int r = blockIdx.x, tid = threadIdx.x;

    // partial sums over all preceding rows
    long long part = 0;
    if (tid < NBLK2) {
        for (int q = 0; q < r; q++)
            part += g_bh[q * NBLK2 + tid];
    }
    sh[tid] = (int)part;
    __syncthreads();
    for (int off = 128; off > 0; off >>= 1) {
        if (tid < off) sh[tid] += sh[tid + off];
        __syncthreads();
    }
    int base = sh[0];
    __syncthreads();

    // exclusive scan of own row (Hillis-Steele over 256; NBLK2 entries)
    int v = (tid < NBLK2) ? g_bh[r * NBLK2 + tid] : 0;
    sh[tid] = v;
    __syncthreads();
    for (int off = 1; off < 256; off <<= 1) {
        int x = (tid >= off) ? sh[tid - off] : 0;
        __syncthreads();
        sh[tid] += x;
        __syncthreads();
    }
    if (tid < NBLK2) g_off[r * NBLK2 + tid] = base + sh[tid] - v;
}

// ---------------------------------------------------------------------------
// Pass 3: scatter with shared cursors (no global atomics)
// ---------------------------------------------------------------------------
__global__ __launch_bounds__(SORT_TPB) void k_scatter(const int* __restrict__ src,
                                                      const int* __restrict__ dst,
                                                      const int* __restrict__ et,
                                                      const float* __restrict__ norm,
                                                      int n, int chunk) {
    __shared__ int cur[MAXR];
    int tid = threadIdx.x, bid = blockIdx.x;
    if (tid < MAXR) cur[tid] = g_off[tid * NBLK2 + bid];
    __syncthreads();
    int lo = bid * chunk;
    int hi = lo + chunk; if (hi > n) hi = n;
    for (int e = lo + tid; e < hi; e += SORT_TPB) {
        int t = et[e];
        int d = dst[e];
        int s = src[e];
        float nv = __ldg(norm + d);
        int pos = atomicAdd(&cur[t], 1);
        int4 ed;
        ed.x = s;
        ed.y = d;
        ed.z = t;
        ed.w = __float_as_int(nv);
        g_edges[pos] = ed;
    }
}

// ---------------------------------------------------------------------------
// Edge kernel (R3 body, EPW=16 — measured faster than 8): warp processes EPW
// consecutive etype-sorted edges; W cached in registers; RED.v4 into d_out.
//   lane l: basis block b = l>>1, output offset o0 = (l&1)*4
// ---------------------------------------------------------------------------
__global__ __launch_bounds__(256) void edge_kernel(
        const float* __restrict__ h,
        const float* __restrict__ weight,
        float* __restrict__ out,
        int nedges) {
    int gw   = (blockIdx.x * blockDim.x + threadIdx.x) >> 5;
    int lane = threadIdx.x & 31;
    int e0 = gw * EPW;
    if (e0 >= nedges) return;            // warp-uniform

    int b  = lane >> 1;
    int o0 = (lane & 1) * 4;

    int t_cur = -1;
    float4 w[SI];

    int e_end = e0 + EPW;
    if (e_end > nedges) e_end = nedges;

    for (int e = e0; e < e_end; e++) {
        int4 ed = g_edges[e];                 // warp-uniform broadcast load
        int s = ed.x, d = ed.y, t = ed.z;
        float nrm = __int_as_float(ed.w);

        if (t != t_cur) {                     // warp-uniform branch (rare)
            t_cur = t;
            const float* wb = weight + (size_t)t * W_PER_REL + b * (SI * SO) + o0;
#pragma unroll
            for (int i = 0; i < SI; i++)
                w[i] = __ldg(reinterpret_cast<const float4*>(wb + i * SO));
        }

        const float4* xp = reinterpret_cast<const float4*>(h + (size_t)s * IN_FEAT + b * SI);
        float4 xa = __ldg(xp);
        float4 xb = __ldg(xp + 1);
        float x[8] = {xa.x, xa.y, xa.z, xa.w, xb.x, xb.y, xb.z, xb.w};

        float4 acc = make_float4(0.f, 0.f, 0.f, 0.f);
#pragma unroll
        for (int i = 0; i < SI; i++) {
            acc.x = fmaf(x[i], w[i].x, acc.x);
            acc.y = fmaf(x[i], w[i].y, acc.y);
            acc.z = fmaf(x[i], w[i].z, acc.z);
            acc.w = fmaf(x[i], w[i].w, acc.w);
        }

        acc.x *= nrm; acc.y *= nrm; acc.z *= nrm; acc.w *= nrm;
        red_add_v4(out + (size_t)d * OUT_FEAT + lane * 4, acc);
    }
}

// ---------------------------------------------------------------------------
// GEMM + add + ReLU (runs LAST): out = relu(h @ lw + out)  — f32x2 FMA.
// 64 rows x 128 cols per block, 256 threads -> thread = 8 rows x 4 cols.
// ---------------------------------------------------------------------------
__global__ __launch_bounds__(256) void gemm_add_relu_kernel(
        const float* __restrict__ h,
        const float* __restrict__ lw,
        float* __restrict__ out) {
    __shared__ float4 xs[GM_ROWS][32];   // 32KB tile of h
    int r0 = blockIdx.x * GM_ROWS;
    int tid = threadIdx.x;

    const float4* h4 = reinterpret_cast<const float4*>(h);
    for (int idx = tid; idx < GM_ROWS * 32; idx += 256) {
        int r = idx >> 5, c = idx & 31;
        int gr = r0 + r;
        xs[r][c] = (gr < N_NODES) ? __ldg(&h4[(size_t)gr * 32 + c])
                                  : make_float4(0.f, 0.f, 0.f, 0.f);
    }
    __syncthreads();

    int cx = tid & 31;          // float4 col index (cols 4cx..4cx+3)
    int rg = (tid >> 5) * 8;    // row base within tile

    uint64_t accA[8], accB[8];
#pragma unroll
    for (int r = 0; r < 8; r++) { accA[r] = 0ull; accB[r] = 0ull; }

    const float4* lw4 = reinterpret_cast<const float4*>(lw);

    for (int k4 = 0; k4 < 32; k4++) {        // 4 k-values per iteration
        float4 w0 = __ldg(&lw4[(size_t)(k4 * 4 + 0) * 32 + cx]);
        float4 w1 = __ldg(&lw4[(size_t)(k4 * 4 + 1) * 32 + cx]);
        float4 w2 = __ldg(&lw4[(size_t)(k4 * 4 + 2) * 32 + cx]);
        float4 w3 = __ldg(&lw4[(size_t)(k4 * 4 + 3) * 32 + cx]);
        uint64_t wA0 = pack2(w0.x, w0.y), wB0 = pack2(w0.z, w0.w);
        uint64_t wA1 = pack2(w1.x, w1.y), wB1 = pack2(w1.z, w1.w);
        uint64_t wA2 = pack2(w2.x, w2.y), wB2 = pack2(w2.z, w2.w);
        uint64_t wA3 = pack2(w3.x, w3.y), wB3 = pack2(w3.z, w3.w);
#pragma unroll
        for (int r = 0; r < 8; r++) {
            float4 xv = xs[rg + r][k4];      // warp-broadcast LDS.128
            uint64_t xx;
            xx = pack2(xv.x, xv.x); ffma2(accA[r], xx, wA0); ffma2(accB[r], xx, wB0);
            xx = pack2(xv.y, xv.y); ffma2(accA[r], xx, wA1); ffma2(accB[r], xx, wB1);
            xx = pack2(xv.z, xv.z); ffma2(accA[r], xx, wA2); ffma2(accB[r], xx, wB2);
            xx = pack2(xv.w, xv.w); ffma2(accA[r], xx, wA3); ffma2(accB[r], xx, wB3);
        }
    }

    float4* out4 = reinterpret_cast<float4*>(out);
#pragma unroll
    for (int r = 0; r < 8; r++) {
        int gr = r0 + rg + r;
        if (gr < N_NODES) {
            size_t idx = (size_t)gr * 32 + cx;
            float4 agg = out4[idx];           // edge aggregation (norm-scaled)
            float4 v;
            float a0, a1, b0, b1;
            unpack2(accA[r], a0, a1);
            unpack2(accB[r], b0, b1);
            v.x = fmaxf(a0 + agg.x, 0.f);
            v.y = fmaxf(a1 + agg.y, 0.f);
            v.z = fmaxf(b0 + agg.z, 0.f);
            v.w = fmaxf(b1 + agg.w, 0.f);
            out4[idx] = v;
        }
    }
}

// ---------------------------------------------------------------------------
// Launch (5 kernels): hist(+zero out) -> scanall -> scatter
//                     -> edge(RED into out) -> gemm+add+relu
// Inputs (metadata order): h, norm, weight, loop_weight, src, dst, etype
// ---------------------------------------------------------------------------
extern "C" void kernel_launch(void* const* d_in, const int* in_sizes, int n_in,
                              void* d_out, int out_size) {
    const float* h      = (const float*)d_in[0];
    const float* norm   = (const float*)d_in[1];
    const float* weight = (const float*)d_in[2];
    const float* lw     = (const float*)d_in[3];
    const int*   src    = (const int*)d_in[4];
    const int*   dst    = (const int*)d_in[5];
    const int*   etype  = (const int*)d_in[6];
    float* out = (float*)d_out;

    int nedges = in_sizes[4];
    if (nedges > E_MAX) nedges = E_MAX;
    int chunk = (nedges + NBLK2 - 1) / NBLK2;

    // ---- counting sort by etype (hist also zeroes d_out) ----
    k_hist<<<NBLK2, SORT_TPB>>>(etype, out, nedges, chunk);
    k_scanall<<<MAXR, 256>>>();
    k_scatter<<<NBLK2, SORT_TPB>>>(src, dst, etype, norm, nedges, chunk);

    // ---- per-edge messages, RED directly into d_out ----
    {
        int nwarps = (nedges + EPW - 1) / EPW;
        int blocks = (nwarps + 7) / 8;       // 8 warps / block
        edge_kernel<<<blocks, 256>>>(h, weight, out, nedges);
    }

    // ---- self-loop GEMM + add + ReLU (final pass) ----
    gemm_add_relu_kernel<<<(N_NODES + GM_ROWS - 1) / GM_ROWS, 256>>>(h, lw, out);
}